// round 4
// baseline (speedup 1.0000x reference)
#include <cuda_runtime.h>
#include <math.h>

#define B_  64
#define LQ  32
#define O_  128
#define LK  256
#define D_  128
#define FULLM 0xffffffffu

// Scratch (device globals)
__device__ float g_invq[B_ * LQ];      // 1/||q_row||
__device__ float g_invk[O_ * LK];      // 1/||k_row||
__device__ int   g_q_active[B_];
__device__ int   g_mask_mode;          // 0=int32, 1=uint8, 2=float32

__device__ __forceinline__ bool mask_at(const void* buf, int idx, int mode) {
    if (mode == 0) return ((const int*)buf)[idx] != 0;
    if (mode == 2) return ((const float*)buf)[idx] != 0.0f;
    return ((const unsigned char*)buf)[idx] != 0;
}

// ---- f32x2 packed helpers -------------------------------------------------
__device__ __forceinline__ unsigned long long pk2(float a, float b) {
    unsigned long long r;
    asm("mov.b64 %0,{%1,%2};" : "=l"(r) : "f"(a), "f"(b));
    return r;
}
__device__ __forceinline__ void fma2(unsigned long long& d,
                                     unsigned long long a, unsigned long long b) {
    asm("fma.rn.f32x2 %0,%1,%2,%0;" : "+l"(d) : "l"(a), "l"(b));
}
__device__ __forceinline__ float2 upk2(unsigned long long v) {
    float2 r;
    asm("mov.b64 {%0,%1},%2;" : "=f"(r.x), "=f"(r.y) : "l"(v));
    return r;
}

// ---------------------------------------------------------------------------
// Kernel 0: sniff mask dtype from first 2048 BYTES of q_mask.
// ---------------------------------------------------------------------------
__global__ void detect_mask_kernel(const unsigned int* __restrict__ qm_words) {
    int l = threadIdx.x;
    bool ok_i32 = true, ok_f32 = true;
    for (int i = l; i < 512; i += 32) {
        unsigned int w = qm_words[i];
        if (w > 1u) ok_i32 = false;
        if (w != 0u && w != 0x3F800000u) ok_f32 = false;
    }
    unsigned bi = __ballot_sync(FULLM, ok_i32);
    unsigned bf = __ballot_sync(FULLM, ok_f32);
    if (l == 0) {
        int mode;
        if (bi == FULLM)      mode = 0;
        else if (bf == FULLM) mode = 2;
        else                  mode = 1;
        g_mask_mode = mode;
    }
}

// ---------------------------------------------------------------------------
// Kernel 1: inverse L2 norms (warp per 128-float row). Writes scalars only.
// ---------------------------------------------------------------------------
__global__ void invnorm_kernel(const float* __restrict__ q,
                               const float* __restrict__ k) {
    int gw   = (blockIdx.x * blockDim.x + threadIdx.x) >> 5;
    int lane = threadIdx.x & 31;
    const int nq = B_ * LQ;
    if (gw >= nq + O_ * LK) return;
    const float* src = (gw < nq) ? q : k;
    int row = (gw < nq) ? gw : gw - nq;
    float4 v = ((const float4*)(src + (size_t)row * D_))[lane];
    float ss = v.x * v.x + v.y * v.y + v.z * v.z + v.w * v.w;
    #pragma unroll
    for (int o = 16; o; o >>= 1) ss += __shfl_xor_sync(FULLM, ss, o);
    if (lane == 0) {
        float inv = 1.0f / fmaxf(sqrtf(ss), 1e-12f);
        if (gw < nq) g_invq[row] = inv; else g_invk[row] = inv;
    }
}

// ---------------------------------------------------------------------------
// Kernel 2: per-batch "no masked query token" flag.
// ---------------------------------------------------------------------------
__global__ void qactive_kernel(const void* __restrict__ qm) {
    int b = blockIdx.x, l = threadIdx.x;
    bool m = mask_at(qm, b * LQ + l, g_mask_mode);
    unsigned bal = __ballot_sync(FULLM, m);
    if (l == 0) g_q_active[b] = (bal == 0u) ? 1 : 0;
}

// ---------------------------------------------------------------------------
// Kernel 3: score. Block = (o_pair, b): covers o0=2*bx, o1=o0+1. 256 thr.
// Warp w: osel=w>>2 picks o, wi=w&3 picks i rows [8wi,8wi+8).
// Lane l owns j in {4l..4l+3} and {128+4l..128+4l+3}.
// k transposed to smem kt[d][j] with granule swizzle g ^= (d>>2)&7:
//   conflict-free on scalar STS scatter AND LDS.128 reads (verified).
// FFMA2 packed math: 32 fma2 per thread per 2-d step.
// ---------------------------------------------------------------------------
__global__ __launch_bounds__(256, 2)
void score_kernel(const float* __restrict__ q,
                  const float* __restrict__ k,
                  const void* __restrict__ k_mask,
                  const float* __restrict__ logit_scale,
                  float* __restrict__ out) {
    const int o0  = blockIdx.x * 2;
    const int b   = blockIdx.y;
    const int tid = threadIdx.x;

    if (!g_q_active[b]) {
        if (tid < 2) out[b * O_ + o0 + tid] = 0.0f;
        return;
    }

    extern __shared__ float smem[];
    float* q_s   = smem;                    // 4096
    float* kt    = q_s + LQ * D_;           // 2 * 8192 (two o tiles, swizzled)
    float* ivk_s = kt + 2 * 32 * LK;        // 512
    float* wm_s  = ivk_s + 2 * LK;          // 512
    float* ivq_s = wm_s + 2 * LK;           // 32
    float* red   = ivq_s + LQ;              // 8

    // Stage q tile [32][128] (row-major), coalesced
    {
        const float4* q4 = (const float4*)(q + (size_t)b * LQ * D_);
        #pragma unroll
        for (int it = 0; it < 4; it++)
            ((float4*)q_s)[it * 256 + tid] = q4[it * 256 + tid];
    }
    if (tid < LQ) ivq_s[tid] = g_invq[b * LQ + tid];
    {
        int mode = g_mask_mode;
        #pragma unroll
        for (int r = 0; r < 2; r++) {
            int idx = r * 256 + tid;            // idx = oo*256 + j
            int oo = idx >> 8, j = idx & 255;
            ivk_s[idx] = g_invk[(o0 + oo) * LK + j];
            wm_s[idx]  = mask_at(k_mask, (o0 + oo) * LK + j, mode) ? 0.0f : 1.0f;
        }
    }

    const int w = tid >> 5, l = tid & 31;
    const int osel = w >> 2, ibase = (w & 3) * 8;
    float* kt_my = kt + osel * (32 * LK);

    unsigned long long acc[8][4];
    #pragma unroll
    for (int ii = 0; ii < 8; ii++)
        #pragma unroll
        for (int p = 0; p < 4; p++) acc[ii][p] = 0ull;

    #pragma unroll 1
    for (int c = 0; c < 4; c++) {           // 4 chunks of 32 d
        __syncthreads();
        // Coalesced load + swizzled transpose of both o tiles.
        #pragma unroll
        for (int oo = 0; oo < 2; oo++) {
            const float4* kr4 = (const float4*)(k + (size_t)(o0 + oo) * LK * D_);
            float* dst = kt + oo * (32 * LK);
            #pragma unroll
            for (int t = 0; t < 8; t++) {
                int j  = t * 32 + (tid >> 3);
                int d4 = tid & 7;
                float4 v = kr4[j * (D_ / 4) + c * 8 + d4];
                int col = (((j >> 2) ^ d4) << 2) + (j & 3);   // swizzled column
                dst[(4 * d4 + 0) * LK + col] = v.x;
                dst[(4 * d4 + 1) * LK + col] = v.y;
                dst[(4 * d4 + 2) * LK + col] = v.z;
                dst[(4 * d4 + 3) * LK + col] = v.w;
            }
        }
        __syncthreads();

        #pragma unroll 4
        for (int d2 = 0; d2 < 16; d2++) {   // 2 d per step
            int d0 = 2 * d2;
            // k for d0 and d0+1 (swizzled reads, conflict-free LDS.128)
            unsigned long long kp0[4], kp1[4];
            {
                int s0 = (d0 >> 2) & 7;
                const float* r0 = kt_my + d0 * LK;
                float4 a = *(const float4*)(r0 + ((l ^ s0) << 2));
                float4 bq = *(const float4*)(r0 + 128 + ((l ^ s0) << 2));
                kp0[0] = pk2(a.x, a.y);  kp0[1] = pk2(a.z, a.w);
                kp0[2] = pk2(bq.x, bq.y); kp0[3] = pk2(bq.z, bq.w);
                int s1 = ((d0 + 1) >> 2) & 7;
                const float* r1 = kt_my + (d0 + 1) * LK;
                float4 c1 = *(const float4*)(r1 + ((l ^ s1) << 2));
                float4 d1 = *(const float4*)(r1 + 128 + ((l ^ s1) << 2));
                kp1[0] = pk2(c1.x, c1.y); kp1[1] = pk2(c1.z, c1.w);
                kp1[2] = pk2(d1.x, d1.y); kp1[3] = pk2(d1.z, d1.w);
            }
            #pragma unroll
            for (int ii = 0; ii < 8; ii++) {
                float2 qv = *(const float2*)(q_s + (ibase + ii) * D_ + c * 32 + d0);
                unsigned long long qd0 = pk2(qv.x, qv.x);
                unsigned long long qd1 = pk2(qv.y, qv.y);
                #pragma unroll
                for (int p = 0; p < 4; p++) fma2(acc[ii][p], qd0, kp0[p]);
                #pragma unroll
                for (int p = 0; p < 4; p++) fma2(acc[ii][p], qd1, kp1[p]);
            }
        }
    }

    // Epilogue: p_i = sum_j wm_j * exp(12 * acc * invq_i * invk_j)
    float4 iva = *(const float4*)(ivk_s + osel * LK + 4 * l);
    float4 ivb = *(const float4*)(ivk_s + osel * LK + 128 + 4 * l);
    float4 wma = *(const float4*)(wm_s + osel * LK + 4 * l);
    float4 wmb = *(const float4*)(wm_s + osel * LK + 128 + 4 * l);
    float lsum = 0.0f;
    #pragma unroll
    for (int ii = 0; ii < 8; ii++) {
        float a12 = 12.0f * ivq_s[ibase + ii];
        float2 f0 = upk2(acc[ii][0]), f1 = upk2(acc[ii][1]);
        float2 f2 = upk2(acc[ii][2]), f3 = upk2(acc[ii][3]);
        float p = wma.x * __expf(a12 * iva.x * f0.x)
                + wma.y * __expf(a12 * iva.y * f0.y)
                + wma.z * __expf(a12 * iva.z * f1.x)
                + wma.w * __expf(a12 * iva.w * f1.y)
                + wmb.x * __expf(a12 * ivb.x * f2.x)
                + wmb.y * __expf(a12 * ivb.y * f2.y)
                + wmb.z * __expf(a12 * ivb.z * f3.x)
                + wmb.w * __expf(a12 * ivb.w * f3.y);
        #pragma unroll
        for (int of = 16; of; of >>= 1) p += __shfl_xor_sync(FULLM, p, of);
        if (l == 0) lsum += __logf(p);
    }
    if (l == 0) red[w] = lsum;
    __syncthreads();

    if (tid < 2) {
        float t = red[tid * 4] + red[tid * 4 + 1] + red[tid * 4 + 2] + red[tid * 4 + 3];
        float s = t * (1.0f / 12.0f);
        s = s / (sqrtf((float)(LQ * LK)) + 1e-6f);
        s *= fminf(expf(logit_scale[0]), 100.0f);
        if (!isfinite(s)) s = 0.0f;
        out[b * O_ + o0 + tid] = s;
    }
}

// ---------------------------------------------------------------------------
extern "C" void kernel_launch(void* const* d_in, const int* in_sizes, int n_in,
                              void* d_out, int out_size) {
    const float* q  = (const float*)d_in[0];
    const float* k  = (const float*)d_in[1];
    const void*  qm = d_in[2];
    const void*  km = d_in[3];
    const float* ls = (const float*)d_in[4];
    float* out = (float*)d_out;

    detect_mask_kernel<<<1, 32>>>((const unsigned int*)qm);

    {
        int nrows = B_ * LQ + O_ * LK;
        invnorm_kernel<<<(nrows + 7) / 8, 256>>>(q, k);
    }
    qactive_kernel<<<B_, 32>>>(qm);

    {
        const int smem_bytes =
            (LQ * D_ + 2 * 32 * LK + 2 * LK + 2 * LK + LQ + 8) * (int)sizeof(float);
        cudaFuncSetAttribute(score_kernel,
                             cudaFuncAttributeMaxDynamicSharedMemorySize,
                             smem_bytes);
        dim3 grid(O_ / 2, B_);
        score_kernel<<<grid, 256, smem_bytes>>>(q, k, km, ls, out);
    }
}